// round 13
// baseline (speedup 1.0000x reference)
#include <cuda_runtime.h>
#include <cuda_fp16.h>
#include <math.h>

// RRoIAlign:
//   K1: NCHW (8,32,160,160) f32 -> NHWC fp16 scratch (8,160,160,32). XOR-swizzled
//       f32 tile; phase2 in 8-channel units: CF LDS + fp16 convert + STG.128.
//   K2: grid (1024 rois, 4 row-pairs) x 512 threads; geometry by 128 threads into
//       smem; thread = (row, 8-ch group, pw): 4 fp16 taps via LDG.128 -> fp32
//       blend -> DIRECT coalesced STG.32 x8 (no staging smem, one sync total).

namespace {

constexpr int PH = 8;
constexpr int PW = 64;
constexpr int CC = 32;
constexpr int HH = 160;
constexpr int WW = 160;
constexpr int BB = 8;
constexpr float SCALE = 0.25f;

constexpr int IMG   = HH * WW * CC;          // 819200 elems per image
constexpr int ROWF  = WW * CC;               // 5120 elems per pixel-row
constexpr int GUARD = 524288;                // zero guard each side

__device__ __half g_nhwc[GUARD + (size_t)BB * IMG + GUARD];

// ---------------- K1: NCHW f32 -> NHWC f16 transpose ----------------
__global__ __launch_bounds__(256) void transpose_kernel(const float* __restrict__ feat)
{
    __shared__ float4 tile[CC * 40];         // [c][sxq], sxq = xq ^ ((c>>2)&7)
    const int b = blockIdx.x / HH;
    const int y = blockIdx.x - b * HH;

    // phase 1: coalesced LDG.128, conflict-free STS.128
    const float4* src = reinterpret_cast<const float4*>(feat + (size_t)b * (HH * WW * CC) + (size_t)y * WW);
#pragma unroll
    for (int f = threadIdx.x; f < CC * 40; f += 256) {       // 5 iters
        const int c  = f / 40;
        const int xq = f - c * 40;
        const int sxq = xq ^ ((c >> 2) & 7);
        tile[c * 40 + sxq] = __ldg(src + (size_t)c * (HH * WW / 4) + xq);
    }
    __syncthreads();

    // phase 2: 8-channel units -> 8 scalar LDS (CF) + fp16 convert + STG.128
    const float* tf = reinterpret_cast<const float*>(tile);
    __half* dst = g_nhwc + GUARD + (size_t)b * IMG + (size_t)y * ROWF;
    for (int g = threadIdx.x; g < (WW * CC) / 8; g += 256) { // 640 items
        const int x   = g >> 2;
        const int cg8 = g & 3;
        const int xq  = x >> 2;
        const int xr  = x & 3;
        float v[8];
#pragma unroll
        for (int j = 0; j < 8; j++) {
            const int c   = 8 * cg8 + j;
            const int sxq = xq ^ ((c >> 2) & 7);
            v[j] = tf[(c * 40 + sxq) * 4 + xr];
        }
        uint4 u;
        __half2 h;
        h = __floats2half2_rn(v[0], v[1]); u.x = *reinterpret_cast<const unsigned int*>(&h);
        h = __floats2half2_rn(v[2], v[3]); u.y = *reinterpret_cast<const unsigned int*>(&h);
        h = __floats2half2_rn(v[4], v[5]); u.z = *reinterpret_cast<const unsigned int*>(&h);
        h = __floats2half2_rn(v[6], v[7]); u.w = *reinterpret_cast<const unsigned int*>(&h);
        *reinterpret_cast<uint4*>(dst + (size_t)x * CC + 8 * cg8) = u;   // 16B, coalesced
    }
}

// convert 8 fp16 (uint4) -> 8 fp32 and FMA into acc with scalar weight
__device__ __forceinline__ void fma8h(float* acc, uint4 u, float w) {
    const __half2* h = reinterpret_cast<const __half2*>(&u);
#pragma unroll
    for (int j = 0; j < 4; j++) {
        const float2 f = __half22float2(h[j]);
        acc[2 * j + 0] += w * f.x;
        acc[2 * j + 1] += w * f.y;
    }
}

// ---------------- K2: gather + blend + direct store, 2 rows per block ----------------
__global__ __launch_bounds__(512) void rroi_gather_kernel(
    const float* __restrict__ rois,
    float* __restrict__ out)
{
    __shared__ int    s_base[2 * PW];         // slot = row_local*64 + pw
    __shared__ float4 s_wv[2 * PW];

    const int n   = blockIdx.x;
    const int tid = threadIdx.x;

    if (tid < 2 * PW) {
        const float2* rp = reinterpret_cast<const float2*>(rois + (size_t)n * 6);
        const float2 ra = __ldg(rp + 0);   // batch_idx, cx
        const float2 rb = __ldg(rp + 1);   // cy, h
        const float2 rc = __ldg(rp + 2);   // w, ang

        const int   bidx = (int)ra.x;
        const float cx = ra.y, cy = rb.x, hh = rb.y, ww = rc.x, ang = rc.y;

        const float theta = ang * 0.017453292519943295f;
        float sa, ca;
        sincosf(theta, &sa, &ca);

        const float Sx = ww * SCALE / (float)PW;
        const float Sy = hh * SCALE / (float)PH;
        const float dxc = -(float)PW * 0.5f;
        const float dyc = -(float)PH * 0.5f;
        const float Dx = cx * SCALE;
        const float Dy = cy * SCALE;

        const float M00 = ca * Sx;
        const float M01 = sa * Sy;
        const float M02 = M00 * dxc + M01 * dyc + Dx;
        const float M10 = -sa * Sx;
        const float M11 = ca * Sy;
        const float M12 = M10 * dxc + M11 * dyc + Dy;

        const float pw  = (float)(tid & (PW - 1));
        const float ph  = (float)(blockIdx.y * 2 + (tid >> 6));
        const float pw1 = pw + 1.0f;
        const float ph1 = ph + 1.0f;

        const float X0 = M00 * pw  + M01 * ph  + M02;
        const float X1 = M00 * pw  + M01 * ph1 + M02;
        const float X2 = M00 * pw1 + M01 * ph  + M02;
        const float X3 = M00 * pw1 + M01 * ph1 + M02;
        const float Y0 = M10 * pw  + M11 * ph  + M12;
        const float Y1 = M10 * pw  + M11 * ph1 + M12;
        const float Y2 = M10 * pw1 + M11 * ph  + M12;
        const float Y3 = M10 * pw1 + M11 * ph1 + M12;

        const float xmn = fminf(fminf(X0, X1), fminf(X2, X3));
        const float xmx = fmaxf(fmaxf(X0, X1), fmaxf(X2, X3));
        const float ymn = fminf(fminf(Y0, Y1), fminf(Y2, Y3));
        const float ymx = fmaxf(fmaxf(Y0, Y1), fmaxf(Y2, Y3));

        const float left   = fmaxf(floorf(xmn + 0.5f), 0.0f);
        const float right  = fminf(floorf(xmx + 0.5f), (float)(WW - 1));
        const float top    = fmaxf(floorf(ymn + 0.5f), 0.0f);
        const float bottom = fminf(floorf(ymx + 0.5f), (float)(HH - 1));

        const float bcx = (left + right) * 0.5f;
        const float bcy = (top + bottom) * 0.5f;

        const float bl = floorf(bcx);
        const float br = ceilf(bcx);
        const float bt = floorf(bcy);
        const float bb = ceilf(bcy);
        const float rx = bcx - bl;
        const float ry = bcy - bt;

        const bool vl = (bl > -1.0f) && (bl < (float)WW);
        const bool vr = (br > -1.0f) && (br < (float)WW);
        const bool vt = (bt > -1.0f) && (bt < (float)HH);
        const bool vb = (bb > -1.0f) && (bb < (float)HH);

        // nonzero weight implies ceil==floor+1 on that axis, so the fixed 2x2
        // patch at (yt..yt+1, xl..xl+1) is exact; zero-weight taps may touch
        // the zeroed guard band harmlessly.
        float wlt = (1.0f - rx) * (1.0f - ry);
        float wrt = rx * (1.0f - ry);
        float wlb = (1.0f - rx) * ry;
        float wrb = rx * ry;
        if (!(vt && vl)) wlt = 0.0f;
        if (!(vt && vr)) wrt = 0.0f;
        if (!(vb && vl)) wlb = 0.0f;
        if (!(vb && vr)) wrb = 0.0f;

        const int xl = (int)bl;
        const int yt = (int)bt;

        s_base[tid] = bidx * IMG + (yt * WW + xl) * CC;
        s_wv[tid]   = make_float4(wlt, wrt, wlb, wrb);
    }
    __syncthreads();

    // thread = (rowl, cg, pw): warp spans 32 consecutive pw at fixed 8-ch group
    const int rowl = tid >> 8;            // 0..1
    const int cg   = (tid >> 6) & 3;      // 8-channel group
    const int pw   = tid & 63;            // 0..63
    const int slot = rowl * PW + pw;

    const __half* g = g_nhwc + GUARD;
    const int base  = s_base[slot] + cg * 8;
    const float4 w  = s_wv[slot];

    const uint4 u00 = *reinterpret_cast<const uint4*>(g + base);
    const uint4 u01 = *reinterpret_cast<const uint4*>(g + base + CC);
    const uint4 u10 = *reinterpret_cast<const uint4*>(g + base + ROWF);
    const uint4 u11 = *reinterpret_cast<const uint4*>(g + base + ROWF + CC);

    float acc[8] = {0, 0, 0, 0, 0, 0, 0, 0};
    fma8h(acc, u00, w.x);
    fma8h(acc, u01, w.y);
    fma8h(acc, u10, w.z);
    fma8h(acc, u11, w.w);

    // direct coalesced stores: per j, warp writes 32 consecutive pw (128B)
    const int row = blockIdx.y * 2 + rowl;
    float* ob = out + (size_t)n * (CC * PH * PW)
                    + (size_t)(cg * 8) * (PH * PW)
                    + (size_t)row * PW + pw;
#pragma unroll
    for (int j = 0; j < 8; j++) {
        ob[(size_t)j * (PH * PW)] = acc[j];
    }
}

}  // namespace

extern "C" void kernel_launch(void* const* d_in, const int* in_sizes, int n_in,
                              void* d_out, int out_size) {
    const float* features = (const float*)d_in[0];
    const float* rois     = (const float*)d_in[1];
    float* out            = (float*)d_out;

    const int N = in_sizes[1] / 6;  // 1024

    transpose_kernel<<<BB * HH, 256>>>(features);
    dim3 grid(N, PH / 2);
    rroi_gather_kernel<<<grid, 512>>>(rois, out);
}

// round 14
// speedup vs baseline: 1.1323x; 1.1323x over previous
#include <cuda_runtime.h>
#include <cuda_fp16.h>
#include <math.h>

// RRoIAlign:
//   K1: NCHW (8,32,160,160) f32 -> NHWC fp16 scratch (8,160,160,32). XOR-swizzled
//       f32 tile in smem; convert to fp16 at the coalesced STG.64.
//   K2: grid (1024 rois, 4 row-pairs) x 512 threads (R12 layout); geometry by 128
//       threads into smem (weights pre-packed as half2); each thread owns one
//       (row,bin) x 8-channel group: 4 taps via LDG.128 fp16 -> 16x HFMA2 blend
//       -> fp32 convert -> stride-65 staging (CF STS); CF epilogue LDS +
//       coalesced STG.128 (fp32 out).

namespace {

constexpr int PH = 8;
constexpr int PW = 64;
constexpr int CC = 32;
constexpr int HH = 160;
constexpr int WW = 160;
constexpr int BB = 8;
constexpr float SCALE = 0.25f;

constexpr int IMG   = HH * WW * CC;          // 819200 elems per image
constexpr int ROWF  = WW * CC;               // 5120 elems per pixel-row
constexpr int GUARD = 524288;                // zero guard each side

__device__ __half g_nhwc[GUARD + (size_t)BB * IMG + GUARD];

// ---------------- K1: NCHW f32 -> NHWC f16 transpose ----------------
__global__ __launch_bounds__(256) void transpose_kernel(const float* __restrict__ feat)
{
    __shared__ float4 tile[CC * 40];         // [c][sxq], sxq = xq ^ ((c>>2)&7)
    const int b = blockIdx.x / HH;
    const int y = blockIdx.x - b * HH;

    // phase 1: coalesced LDG.128, conflict-free STS.128
    const float4* src = reinterpret_cast<const float4*>(feat + (size_t)b * (HH * WW * CC) + (size_t)y * WW);
#pragma unroll
    for (int f = threadIdx.x; f < CC * 40; f += 256) {       // 5 iters
        const int c  = f / 40;
        const int xq = f - c * 40;
        const int sxq = xq ^ ((c >> 2) & 7);
        tile[c * 40 + sxq] = __ldg(src + (size_t)c * (HH * WW / 4) + xq);
    }
    __syncthreads();

    // phase 2: 4 scalar LDS (CF) -> f16 convert -> coalesced STG.64
    const float* tf = reinterpret_cast<const float*>(tile);
    __half* dst = g_nhwc + GUARD + (size_t)b * IMG + (size_t)y * ROWF;
#pragma unroll
    for (int g = threadIdx.x; g < (WW * CC) / 4; g += 256) { // 5 iters
        const int x  = g >> 3;
        const int cg = g & 7;
        const int xq = x >> 2;
        const int xr = x & 3;
        const int sxq = xq ^ cg;             // ((4cg+j)>>2)&7 == cg for j<4
        float4 v;
        v.x = tf[((4 * cg + 0) * 40 + sxq) * 4 + xr];
        v.y = tf[((4 * cg + 1) * 40 + sxq) * 4 + xr];
        v.z = tf[((4 * cg + 2) * 40 + sxq) * 4 + xr];
        v.w = tf[((4 * cg + 3) * 40 + sxq) * 4 + xr];
        const __half2 h0 = __floats2half2_rn(v.x, v.y);
        const __half2 h1 = __floats2half2_rn(v.z, v.w);
        uint2 u;
        u.x = *reinterpret_cast<const unsigned int*>(&h0);
        u.y = *reinterpret_cast<const unsigned int*>(&h1);
        *reinterpret_cast<uint2*>(dst + (size_t)x * CC + 4 * cg) = u;   // 8B, coalesced
    }
}

// acc[j] += u.h2[j] * w  (packed fp16, 4x HFMA2)
__device__ __forceinline__ void fma8h2(__half2* acc, uint4 u, __half2 w) {
    const __half2* h = reinterpret_cast<const __half2*>(&u);
#pragma unroll
    for (int j = 0; j < 4; j++) acc[j] = __hfma2(h[j], w, acc[j]);
}

// ---------------- K2: gather + blend, 2 rows per block, single pass ----------------
__global__ __launch_bounds__(512) void rroi_gather_kernel(
    const float* __restrict__ rois,
    float* __restrict__ out)
{
    __shared__ int   s_base[2 * PW];          // slot = row_local*64 + pw
    __shared__ uint4 s_wh[2 * PW];            // 4 weights as duplicated half2
    __shared__ float s_r[2][CC * 65];         // staging, odd stride (CF STS)

    const int n   = blockIdx.x;
    const int tid = threadIdx.x;

    if (tid < 2 * PW) {
        const float2* rp = reinterpret_cast<const float2*>(rois + (size_t)n * 6);
        const float2 ra = __ldg(rp + 0);   // batch_idx, cx
        const float2 rb = __ldg(rp + 1);   // cy, h
        const float2 rc = __ldg(rp + 2);   // w, ang

        const int   bidx = (int)ra.x;
        const float cx = ra.y, cy = rb.x, hh = rb.y, ww = rc.x, ang = rc.y;

        const float theta = ang * 0.017453292519943295f;
        float sa, ca;
        sincosf(theta, &sa, &ca);

        const float Sx = ww * SCALE / (float)PW;
        const float Sy = hh * SCALE / (float)PH;
        const float dxc = -(float)PW * 0.5f;
        const float dyc = -(float)PH * 0.5f;
        const float Dx = cx * SCALE;
        const float Dy = cy * SCALE;

        const float M00 = ca * Sx;
        const float M01 = sa * Sy;
        const float M02 = M00 * dxc + M01 * dyc + Dx;
        const float M10 = -sa * Sx;
        const float M11 = ca * Sy;
        const float M12 = M10 * dxc + M11 * dyc + Dy;

        const float pw  = (float)(tid & (PW - 1));
        const float ph  = (float)(blockIdx.y * 2 + (tid >> 6));
        const float pw1 = pw + 1.0f;
        const float ph1 = ph + 1.0f;

        const float X0 = M00 * pw  + M01 * ph  + M02;
        const float X1 = M00 * pw  + M01 * ph1 + M02;
        const float X2 = M00 * pw1 + M01 * ph  + M02;
        const float X3 = M00 * pw1 + M01 * ph1 + M02;
        const float Y0 = M10 * pw  + M11 * ph  + M12;
        const float Y1 = M10 * pw  + M11 * ph1 + M12;
        const float Y2 = M10 * pw1 + M11 * ph  + M12;
        const float Y3 = M10 * pw1 + M11 * ph1 + M12;

        const float xmn = fminf(fminf(X0, X1), fminf(X2, X3));
        const float xmx = fmaxf(fmaxf(X0, X1), fmaxf(X2, X3));
        const float ymn = fminf(fminf(Y0, Y1), fminf(Y2, Y3));
        const float ymx = fmaxf(fmaxf(Y0, Y1), fmaxf(Y2, Y3));

        const float left   = fmaxf(floorf(xmn + 0.5f), 0.0f);
        const float right  = fminf(floorf(xmx + 0.5f), (float)(WW - 1));
        const float top    = fmaxf(floorf(ymn + 0.5f), 0.0f);
        const float bottom = fminf(floorf(ymx + 0.5f), (float)(HH - 1));

        const float bcx = (left + right) * 0.5f;
        const float bcy = (top + bottom) * 0.5f;

        const float bl = floorf(bcx);
        const float br = ceilf(bcx);
        const float bt = floorf(bcy);
        const float bb = ceilf(bcy);
        const float rx = bcx - bl;
        const float ry = bcy - bt;

        const bool vl = (bl > -1.0f) && (bl < (float)WW);
        const bool vr = (br > -1.0f) && (br < (float)WW);
        const bool vt = (bt > -1.0f) && (bt < (float)HH);
        const bool vb = (bb > -1.0f) && (bb < (float)HH);

        // nonzero weight implies ceil==floor+1 on that axis, so the fixed 2x2
        // patch at (yt..yt+1, xl..xl+1) is exact; zero-weight taps may touch
        // the zeroed guard band harmlessly.
        float wlt = (1.0f - rx) * (1.0f - ry);
        float wrt = rx * (1.0f - ry);
        float wlb = (1.0f - rx) * ry;
        float wrb = rx * ry;
        if (!(vt && vl)) wlt = 0.0f;
        if (!(vt && vr)) wrt = 0.0f;
        if (!(vb && vl)) wlb = 0.0f;
        if (!(vb && vr)) wrb = 0.0f;

        const int xl = (int)bl;
        const int yt = (int)bt;

        s_base[tid] = bidx * IMG + (yt * WW + xl) * CC;

        uint4 wu;
        __half2 h;
        h = __float2half2_rn(wlt); wu.x = *reinterpret_cast<const unsigned int*>(&h);
        h = __float2half2_rn(wrt); wu.y = *reinterpret_cast<const unsigned int*>(&h);
        h = __float2half2_rn(wlb); wu.z = *reinterpret_cast<const unsigned int*>(&h);
        h = __float2half2_rn(wrb); wu.w = *reinterpret_cast<const unsigned int*>(&h);
        s_wh[tid] = wu;
    }
    __syncthreads();

    // one thread = one (row,bin) x 8-channel group (R12 layout)
    const int rb   = tid >> 2;           // 0..127: row_local*64 + bin
    const int cg   = tid & 3;            // 8-channel group
    const int rowl = rb >> 6;
    const int bin  = rb & 63;

    const __half* g = g_nhwc + GUARD;
    const int base = s_base[rb] + cg * 8;
    const uint4 wu = s_wh[rb];

    const uint4 u00 = *reinterpret_cast<const uint4*>(g + base);
    const uint4 u01 = *reinterpret_cast<const uint4*>(g + base + CC);
    const uint4 u10 = *reinterpret_cast<const uint4*>(g + base + ROWF);
    const uint4 u11 = *reinterpret_cast<const uint4*>(g + base + ROWF + CC);

    __half2 acc[4];
    const __half2 z = __float2half2_rn(0.0f);
#pragma unroll
    for (int j = 0; j < 4; j++) acc[j] = z;

    fma8h2(acc, u00, *reinterpret_cast<const __half2*>(&wu.x));
    fma8h2(acc, u01, *reinterpret_cast<const __half2*>(&wu.y));
    fma8h2(acc, u10, *reinterpret_cast<const __half2*>(&wu.z));
    fma8h2(acc, u11, *reinterpret_cast<const __half2*>(&wu.w));

    const int c0 = cg * 8;
#pragma unroll
    for (int j = 0; j < 4; j++) {
        const float2 f = __half22float2(acc[j]);
        // bank = (c0+2j[+1]) + bin mod 32: lanes all distinct -> CF
        s_r[rowl][(c0 + 2 * j + 0) * 65 + bin] = f.x;
        s_r[rowl][(c0 + 2 * j + 1) * 65 + bin] = f.y;
    }
    __syncthreads();

    // epilogue: warp = 4 c-values x 8 x4-values -> CF LDS + coalesced STG.128
    const int w_id = tid >> 5;
    const int lane = tid & 31;
    const int c  = ((w_id & 7) << 2) + (lane >> 3);   // 0..31
    const int x4 = ((w_id >> 3) << 3) + (lane & 7);   // 0..15
    const int r0 = blockIdx.y * 2;
    float* ob = out + (size_t)n * (CC * PH * PW) + (size_t)c * (PH * PW);

#pragma unroll
    for (int rl = 0; rl < 2; rl++) {
        const float* sr = &s_r[rl][c * 65 + x4 * 4];
        float4 v;
        v.x = sr[0];
        v.y = sr[1];
        v.z = sr[2];
        v.w = sr[3];
        *reinterpret_cast<float4*>(ob + (r0 + rl) * PW + x4 * 4) = v;
    }
}

}  // namespace

extern "C" void kernel_launch(void* const* d_in, const int* in_sizes, int n_in,
                              void* d_out, int out_size) {
    const float* features = (const float*)d_in[0];
    const float* rois     = (const float*)d_in[1];
    float* out            = (float*)d_out;

    const int N = in_sizes[1] / 6;  // 1024

    transpose_kernel<<<BB * HH, 256>>>(features);
    dim3 grid(N, PH / 2);
    rroi_gather_kernel<<<grid, 512>>>(rois, out);
}

// round 17
// speedup vs baseline: 1.2000x; 1.0598x over previous
#include <cuda_runtime.h>
#include <cuda_fp16.h>
#include <math.h>

// RRoIAlign:
//   K1: NCHW (8,32,160,160) f32 -> NHWC fp16 scratch (8,160,160,32). XOR-swizzled
//       f32 tile in smem; convert to fp16 at the coalesced STG.64.
//   K2: grid (1024 rois, 4 row-pairs) x 512 threads; geometry by 128 threads into
//       smem (weights pre-packed half2); thread = (row,bin) x 8-ch group:
//       4 fp16 taps via LDG.128 -> 16x HFMA2 -> acc STAYS half2 -> 4x STS.32
//       (stride-66, CF) -> epilogue: CF/broadcast LDS + half->f32 + STG.128.

namespace {

constexpr int PH = 8;
constexpr int PW = 64;
constexpr int CC = 32;
constexpr int HH = 160;
constexpr int WW = 160;
constexpr int BB = 8;
constexpr float SCALE = 0.25f;

constexpr int IMG   = HH * WW * CC;          // 819200 elems per image
constexpr int ROWF  = WW * CC;               // 5120 elems per pixel-row
constexpr int GUARD = 524288;                // zero guard each side

__device__ __half g_nhwc[GUARD + (size_t)BB * IMG + GUARD];

// ---------------- K1: NCHW f32 -> NHWC f16 transpose ----------------
__global__ __launch_bounds__(256) void transpose_kernel(const float* __restrict__ feat)
{
    __shared__ float4 tile[CC * 40];         // [c][sxq], sxq = xq ^ ((c>>2)&7)
    const int b = blockIdx.x / HH;
    const int y = blockIdx.x - b * HH;

    // phase 1: coalesced LDG.128, conflict-free STS.128
    const float4* src = reinterpret_cast<const float4*>(feat + (size_t)b * (HH * WW * CC) + (size_t)y * WW);
#pragma unroll
    for (int f = threadIdx.x; f < CC * 40; f += 256) {       // 5 iters
        const int c  = f / 40;
        const int xq = f - c * 40;
        const int sxq = xq ^ ((c >> 2) & 7);
        tile[c * 40 + sxq] = __ldg(src + (size_t)c * (HH * WW / 4) + xq);
    }
    __syncthreads();

    // phase 2: 4 scalar LDS (CF) -> f16 convert -> coalesced STG.64
    const float* tf = reinterpret_cast<const float*>(tile);
    __half* dst = g_nhwc + GUARD + (size_t)b * IMG + (size_t)y * ROWF;
#pragma unroll
    for (int g = threadIdx.x; g < (WW * CC) / 4; g += 256) { // 5 iters
        const int x  = g >> 3;
        const int cg = g & 7;
        const int xq = x >> 2;
        const int xr = x & 3;
        const int sxq = xq ^ cg;             // ((4cg+j)>>2)&7 == cg for j<4
        float4 v;
        v.x = tf[((4 * cg + 0) * 40 + sxq) * 4 + xr];
        v.y = tf[((4 * cg + 1) * 40 + sxq) * 4 + xr];
        v.z = tf[((4 * cg + 2) * 40 + sxq) * 4 + xr];
        v.w = tf[((4 * cg + 3) * 40 + sxq) * 4 + xr];
        const __half2 h0 = __floats2half2_rn(v.x, v.y);
        const __half2 h1 = __floats2half2_rn(v.z, v.w);
        uint2 u;
        u.x = *reinterpret_cast<const unsigned int*>(&h0);
        u.y = *reinterpret_cast<const unsigned int*>(&h1);
        *reinterpret_cast<uint2*>(dst + (size_t)x * CC + 4 * cg) = u;   // 8B, coalesced
    }
}

// acc[j] += u.h2[j] * w  (packed fp16, 4x HFMA2)
__device__ __forceinline__ void fma8h2(__half2* acc, uint4 u, __half2 w) {
    const __half2* h = reinterpret_cast<const __half2*>(&u);
#pragma unroll
    for (int j = 0; j < 4; j++) acc[j] = __hfma2(h[j], w, acc[j]);
}

// ---------------- K2: gather + blend, 2 rows per block, single pass ----------------
__global__ __launch_bounds__(512) void rroi_gather_kernel(
    const float* __restrict__ rois,
    float* __restrict__ out)
{
    __shared__ int      s_base[2 * PW];       // slot = row_local*64 + pw
    __shared__ uint4    s_wh[2 * PW];         // 4 weights as duplicated half2
    __shared__ unsigned s_h[2][(CC / 2) * 66]; // half2 staging, stride 66 (CF STS)

    const int n   = blockIdx.x;
    const int tid = threadIdx.x;

    if (tid < 2 * PW) {
        const float2* rp = reinterpret_cast<const float2*>(rois + (size_t)n * 6);
        const float2 ra = __ldg(rp + 0);   // batch_idx, cx
        const float2 rb = __ldg(rp + 1);   // cy, h
        const float2 rc = __ldg(rp + 2);   // w, ang

        const int   bidx = (int)ra.x;
        const float cx = ra.y, cy = rb.x, hh = rb.y, ww = rc.x, ang = rc.y;

        const float theta = ang * 0.017453292519943295f;
        float sa, ca;
        sincosf(theta, &sa, &ca);

        const float Sx = ww * SCALE / (float)PW;
        const float Sy = hh * SCALE / (float)PH;
        const float dxc = -(float)PW * 0.5f;
        const float dyc = -(float)PH * 0.5f;
        const float Dx = cx * SCALE;
        const float Dy = cy * SCALE;

        const float M00 = ca * Sx;
        const float M01 = sa * Sy;
        const float M02 = M00 * dxc + M01 * dyc + Dx;
        const float M10 = -sa * Sx;
        const float M11 = ca * Sy;
        const float M12 = M10 * dxc + M11 * dyc + Dy;

        const float pw  = (float)(tid & (PW - 1));
        const float ph  = (float)(blockIdx.y * 2 + (tid >> 6));
        const float pw1 = pw + 1.0f;
        const float ph1 = ph + 1.0f;

        const float X0 = M00 * pw  + M01 * ph  + M02;
        const float X1 = M00 * pw  + M01 * ph1 + M02;
        const float X2 = M00 * pw1 + M01 * ph  + M02;
        const float X3 = M00 * pw1 + M01 * ph1 + M02;
        const float Y0 = M10 * pw  + M11 * ph  + M12;
        const float Y1 = M10 * pw  + M11 * ph1 + M12;
        const float Y2 = M10 * pw1 + M11 * ph  + M12;
        const float Y3 = M10 * pw1 + M11 * ph1 + M12;

        const float xmn = fminf(fminf(X0, X1), fminf(X2, X3));
        const float xmx = fmaxf(fmaxf(X0, X1), fmaxf(X2, X3));
        const float ymn = fminf(fminf(Y0, Y1), fminf(Y2, Y3));
        const float ymx = fmaxf(fmaxf(Y0, Y1), fmaxf(Y2, Y3));

        const float left   = fmaxf(floorf(xmn + 0.5f), 0.0f);
        const float right  = fminf(floorf(xmx + 0.5f), (float)(WW - 1));
        const float top    = fmaxf(floorf(ymn + 0.5f), 0.0f);
        const float bottom = fminf(floorf(ymx + 0.5f), (float)(HH - 1));

        const float bcx = (left + right) * 0.5f;
        const float bcy = (top + bottom) * 0.5f;

        const float bl = floorf(bcx);
        const float br = ceilf(bcx);
        const float bt = floorf(bcy);
        const float bb = ceilf(bcy);
        const float rx = bcx - bl;
        const float ry = bcy - bt;

        const bool vl = (bl > -1.0f) && (bl < (float)WW);
        const bool vr = (br > -1.0f) && (br < (float)WW);
        const bool vt = (bt > -1.0f) && (bt < (float)HH);
        const bool vb = (bb > -1.0f) && (bb < (float)HH);

        // nonzero weight implies ceil==floor+1 on that axis, so the fixed 2x2
        // patch at (yt..yt+1, xl..xl+1) is exact; zero-weight taps may touch
        // the zeroed guard band harmlessly.
        float wlt = (1.0f - rx) * (1.0f - ry);
        float wrt = rx * (1.0f - ry);
        float wlb = (1.0f - rx) * ry;
        float wrb = rx * ry;
        if (!(vt && vl)) wlt = 0.0f;
        if (!(vt && vr)) wrt = 0.0f;
        if (!(vb && vl)) wlb = 0.0f;
        if (!(vb && vr)) wrb = 0.0f;

        const int xl = (int)bl;
        const int yt = (int)bt;

        s_base[tid] = bidx * IMG + (yt * WW + xl) * CC;

        uint4 wu;
        __half2 h;
        h = __float2half2_rn(wlt); wu.x = *reinterpret_cast<const unsigned int*>(&h);
        h = __float2half2_rn(wrt); wu.y = *reinterpret_cast<const unsigned int*>(&h);
        h = __float2half2_rn(wlb); wu.z = *reinterpret_cast<const unsigned int*>(&h);
        h = __float2half2_rn(wrb); wu.w = *reinterpret_cast<const unsigned int*>(&h);
        s_wh[tid] = wu;
    }
    __syncthreads();

    // one thread = one (row,bin) x 8-channel group
    const int rb   = tid >> 2;           // 0..127: row_local*64 + bin
    const int cg   = tid & 3;            // 8-channel group
    const int rowl = rb >> 6;
    const int bin  = rb & 63;

    const __half* g = g_nhwc + GUARD;
    const int base = s_base[rb] + cg * 8;
    const uint4 wu = s_wh[rb];

    const uint4 u00 = *reinterpret_cast<const uint4*>(g + base);
    const uint4 u01 = *reinterpret_cast<const uint4*>(g + base + CC);
    const uint4 u10 = *reinterpret_cast<const uint4*>(g + base + ROWF);
    const uint4 u11 = *reinterpret_cast<const uint4*>(g + base + ROWF + CC);

    __half2 acc[4];
    const __half2 z = __float2half2_rn(0.0f);
#pragma unroll
    for (int j = 0; j < 4; j++) acc[j] = z;

    fma8h2(acc, u00, *reinterpret_cast<const __half2*>(&wu.x));
    fma8h2(acc, u01, *reinterpret_cast<const __half2*>(&wu.y));
    fma8h2(acc, u10, *reinterpret_cast<const __half2*>(&wu.z));
    fma8h2(acc, u11, *reinterpret_cast<const __half2*>(&wu.w));

    // stage raw half2: pair p = 4cg+j holds channels (2p, 2p+1) at this bin.
    // bank = (66p + bin) mod 32 = (2p + bin) = 8cg + 2j + bin -> CF per j.
#pragma unroll
    for (int j = 0; j < 4; j++) {
        s_h[rowl][(cg * 4 + j) * 66 + bin] = *reinterpret_cast<const unsigned int*>(&acc[j]);
    }
    __syncthreads();

    // epilogue: warp = 4 c-values x 8 x4-values.
    //   LDS word (p = c>>1, x): lanes sharing a pair-word broadcast (free);
    //   banks (c&~1) + 4*x4 + k cover all 32 -> CF.  Then half->f32 + STG.128.
    const int w_id = tid >> 5;
    const int lane = tid & 31;
    const int c  = ((w_id & 7) << 2) + (lane >> 3);   // 0..31
    const int x4 = ((w_id >> 3) << 3) + (lane & 7);   // 0..15
    const int p  = c >> 1;
    const bool hi = (c & 1) != 0;
    const int r0 = blockIdx.y * 2;
    float* ob = out + (size_t)n * (CC * PH * PW) + (size_t)c * (PH * PW);

#pragma unroll
    for (int rl = 0; rl < 2; rl++) {
        const unsigned* sp = &s_h[rl][p * 66 + x4 * 4];
        float4 v;
#pragma unroll
        for (int k = 0; k < 4; k++) {
            const unsigned u = sp[k];
            const __half2 h = *reinterpret_cast<const __half2*>(&u);
            (&v.x)[k] = hi ? __high2float(h) : __low2float(h);
        }
        *reinterpret_cast<float4*>(ob + (r0 + rl) * PW + x4 * 4) = v;
    }
}

}  // namespace

extern "C" void kernel_launch(void* const* d_in, const int* in_sizes, int n_in,
                              void* d_out, int out_size) {
    const float* features = (const float*)d_in[0];
    const float* rois     = (const float*)d_in[1];
    float* out            = (float*)d_out;

    const int N = in_sizes[1] / 6;  // 1024

    transpose_kernel<<<BB * HH, 256>>>(features);
    dim3 grid(N, PH / 2);
    rroi_gather_kernel<<<grid, 512>>>(rois, out);
}